// round 3
// baseline (speedup 1.0000x reference)
#include <cuda_runtime.h>

// S5 associative scan, single-pass decoupled lookback.
//   (A_i,Bu_i)*(A_j,Bu_j) = (A_j*A_i, A_j*Bu_i + Bu_j)
// Per channel d:  cumA_t = A_t * cumA_{t-1},  S_t = A_t*S_{t-1} + Bu_t
// out[0:T*D] = A_scan, out[T*D:2*T*D] = Bu_scan.

#define TT 131072
#define DD 256
#define RR 32                 // rows per chunk (held in registers)
#define GG (TT / RR)          // 4096 chunks / blocks

// Scratch (static device arrays — no runtime allocation).
__device__ float g_aggA[GG * DD];
__device__ float g_aggS[GG * DD];
__device__ float g_incA[GG * DD];
__device__ float g_incS[GG * DD];
__device__ int   g_flag[GG];   // 0 = none, 1 = aggregate ready, 2 = inclusive ready

__device__ __forceinline__ int ld_acq(const int* p) {
    int v;
    asm volatile("ld.global.acquire.gpu.b32 %0, [%1];" : "=r"(v) : "l"(p) : "memory");
    return v;
}
__device__ __forceinline__ void st_rel(int* p, int v) {
    asm volatile("st.global.release.gpu.b32 [%0], %1;" :: "l"(p), "r"(v) : "memory");
}
__device__ __forceinline__ float ld_cg(const float* p) {
    float v;
    asm volatile("ld.global.cg.f32 %0, [%1];" : "=f"(v) : "l"(p) : "memory");
    return v;
}
__device__ __forceinline__ void st_cg(float* p, float v) {
    asm volatile("st.global.cg.f32 [%0], %1;" :: "l"(p), "f"(v) : "memory");
}

__global__ void s5_init() {
    int i = blockIdx.x * blockDim.x + threadIdx.x;
    if (i < GG) g_flag[i] = 0;
}

__global__ __launch_bounds__(DD, 2) void s5_scan(const float* __restrict__ A,
                                                 const float* __restrict__ Bu,
                                                 float* __restrict__ outA,
                                                 float* __restrict__ outS) {
    const int c = blockIdx.x;         // chunk index (time)
    const int d = threadIdx.x;        // channel
    const size_t base = (size_t)c * RR * DD + d;

    // ---- upsweep: local scan held in registers ----
    float cumA[RR], sloc[RR];
    float aA = 1.0f, s = 0.0f;
#pragma unroll
    for (int t = 0; t < RR; ++t) {
        const size_t idx = base + (size_t)t * DD;
        const float a  = __ldcs(A + idx);
        const float bu = __ldcs(Bu + idx);
        aA = aA * a;
        s  = fmaf(a, s, bu);
        cumA[t] = aA;
        sloc[t] = s;
    }

    const int slot = c * DD + d;
    float eA = 1.0f, eS = 0.0f;       // exclusive prefix for this chunk

    if (c == 0) {
        st_cg(&g_incA[slot], aA);
        st_cg(&g_incS[slot], s);
        __threadfence();
        __syncthreads();
        if (d == 0) st_rel(&g_flag[0], 2);
    } else {
        // publish aggregate so successors can make progress
        st_cg(&g_aggA[slot], aA);
        st_cg(&g_aggS[slot], s);
        __threadfence();
        __syncthreads();
        if (d == 0) st_rel(&g_flag[c], 1);

        // ---- per-warp decoupled lookback ----
        // (rA, rS) = combine of chunks (p+1 .. c-1), walked backwards.
        float rA = 1.0f, rS = 0.0f;
        int p = c - 1;
        for (;;) {
            int f;
            do { f = ld_acq(&g_flag[p]); } while (f == 0);
            f = (int)__reduce_min_sync(0xffffffffu, (unsigned)f);  // keep warp converged
            if (f == 2) {
                const float iA = ld_cg(&g_incA[p * DD + d]);
                const float iS = ld_cg(&g_incS[p * DD + d]);
                eA = rA * iA;
                eS = fmaf(rA, iS, rS);
                break;
            } else {
                const float gA = ld_cg(&g_aggA[p * DD + d]);
                const float gS = ld_cg(&g_aggS[p * DD + d]);
                rS = fmaf(rA, gS, rS);
                rA = rA * gA;
                --p;
            }
        }

        // publish inclusive prefix (chunks 0..c)
        const float iA = aA * eA;
        const float iS = fmaf(aA, eS, s);
        st_cg(&g_incA[slot], iA);
        st_cg(&g_incS[slot], iS);
        __threadfence();
        __syncthreads();
        if (d == 0) st_rel(&g_flag[c], 2);
    }

    // ---- downsweep: apply prefix, write outputs (no input re-read) ----
#pragma unroll
    for (int t = 0; t < RR; ++t) {
        const size_t idx = base + (size_t)t * DD;
        __stcs(outA + idx, cumA[t] * eA);
        __stcs(outS + idx, fmaf(cumA[t], eS, sloc[t]));
    }
}

extern "C" void kernel_launch(void* const* d_in, const int* in_sizes, int n_in,
                              void* d_out, int out_size) {
    const float* A  = (const float*)d_in[0];
    const float* Bu = (const float*)d_in[1];
    float* outA = (float*)d_out;
    float* outS = (float*)d_out + (size_t)TT * DD;

    s5_init<<<GG / 256, 256>>>();
    s5_scan<<<GG, DD>>>(A, Bu, outA, outS);
}

// round 4
// speedup vs baseline: 1.6711x; 1.6711x over previous
#include <cuda_runtime.h>

// S5 associative scan: (A_i,Bu_i)*(A_j,Bu_j) = (A_j*A_i, A_j*Bu_i + Bu_j)
// Per channel d:  cumA_t = A_t * cumA_{t-1},   S_t = A_t*S_{t-1} + Bu_t
// out[0:T*D] = A_scan, out[T*D:2*T*D] = Bu_scan.
//
// 3-pass chunked scan, float4-vectorized (thread = 4 channels):
//   pass1: per-chunk aggregates (stored channel-major for pass2 coalescing)
//   pass2: 256 blocks (one per channel), Kogge-Stone over 1024 chunk aggs
//          (stores EXCLUSIVE prefixes chunk-major for pass3 coalescing)
//   pass3: rescan chunks seeded with prefix, write outputs.

#define TT 131072
#define DD 256
#define GG 1024              // time chunks
#define LL (TT / GG)         // 128 rows per chunk
#define V4 (DD / 4)          // 64 float4 per row

// Scratch (static device arrays — allocation rules).
__device__ float g_aggA[DD * GG];    // [d][c]  channel-major
__device__ float g_aggS[DD * GG];
__device__ float g_prefA[GG * DD];   // [c][d]  chunk-major (exclusive prefix)
__device__ float g_prefS[GG * DD];

// ---------------- pass 1: per-chunk aggregates ----------------
__global__ __launch_bounds__(V4) void s5_pass1(const float4* __restrict__ A4,
                                               const float4* __restrict__ Bu4) {
    const int c = blockIdx.x;
    const int t = threadIdx.x;              // channel group: channels 4t..4t+3
    const size_t base = (size_t)c * LL * V4 + t;

    float4 aA = make_float4(1.f, 1.f, 1.f, 1.f);
    float4 s  = make_float4(0.f, 0.f, 0.f, 0.f);
#pragma unroll 8
    for (int i = 0; i < LL; ++i) {
        const float4 a  = __ldcs(A4 + base + (size_t)i * V4);
        const float4 bu = __ldcs(Bu4 + base + (size_t)i * V4);
        aA.x *= a.x; aA.y *= a.y; aA.z *= a.z; aA.w *= a.w;
        s.x = fmaf(a.x, s.x, bu.x);
        s.y = fmaf(a.y, s.y, bu.y);
        s.z = fmaf(a.z, s.z, bu.z);
        s.w = fmaf(a.w, s.w, bu.w);
    }
    const int d = 4 * t;
    g_aggA[(d + 0) * GG + c] = aA.x;
    g_aggA[(d + 1) * GG + c] = aA.y;
    g_aggA[(d + 2) * GG + c] = aA.z;
    g_aggA[(d + 3) * GG + c] = aA.w;
    g_aggS[(d + 0) * GG + c] = s.x;
    g_aggS[(d + 1) * GG + c] = s.y;
    g_aggS[(d + 2) * GG + c] = s.z;
    g_aggS[(d + 3) * GG + c] = s.w;
}

// ---------------- pass 2: cross-chunk scan (one block per channel) ----------
__global__ __launch_bounds__(GG) void s5_pass2() {
    __shared__ float shA[GG];
    __shared__ float shS[GG];
    const int d = blockIdx.x;
    const int c = threadIdx.x;

    float vA = g_aggA[d * GG + c];          // coalesced
    float vS = g_aggS[d * GG + c];
    shA[c] = vA;
    shS[c] = vS;
    __syncthreads();

    // Kogge-Stone inclusive scan over c: new[c] = op(old[c-off], old[c])
    //   op((Ax,Sx) earlier, (Ay,Sy) later) = (Ay*Ax, Ay*Sx + Sy)
#pragma unroll
    for (int off = 1; off < GG; off <<= 1) {
        float pA = 0.f, pS = 0.f;
        if (c >= off) { pA = shA[c - off]; pS = shS[c - off]; }
        __syncthreads();
        if (c >= off) {
            vS = fmaf(vA, pS, vS);
            vA = vA * pA;
            shA[c] = vA;
            shS[c] = vS;
        }
        __syncthreads();
    }

    // exclusive prefix for chunk c = inclusive of c-1
    const float eA = (c == 0) ? 1.f : shA[c - 1];
    const float eS = (c == 0) ? 0.f : shS[c - 1];
    g_prefA[c * DD + d] = eA;               // chunk-major for pass3
    g_prefS[c * DD + d] = eS;
}

// ---------------- pass 3: rescan with prefix, write outputs -----------------
__global__ __launch_bounds__(V4) void s5_pass3(const float4* __restrict__ A4,
                                               const float4* __restrict__ Bu4,
                                               float4* __restrict__ outA4,
                                               float4* __restrict__ outS4) {
    const int c = blockIdx.x;
    const int t = threadIdx.x;
    const size_t base = (size_t)c * LL * V4 + t;

    const float4* pref4A = (const float4*)g_prefA;
    const float4* pref4S = (const float4*)g_prefS;
    float4 aA = pref4A[c * V4 + t];         // coalesced
    float4 s  = pref4S[c * V4 + t];

#pragma unroll 8
    for (int i = 0; i < LL; ++i) {
        const size_t idx = base + (size_t)i * V4;
        const float4 a  = __ldcs(A4 + idx);
        const float4 bu = __ldcs(Bu4 + idx);
        aA.x *= a.x; aA.y *= a.y; aA.z *= a.z; aA.w *= a.w;
        s.x = fmaf(a.x, s.x, bu.x);
        s.y = fmaf(a.y, s.y, bu.y);
        s.z = fmaf(a.z, s.z, bu.z);
        s.w = fmaf(a.w, s.w, bu.w);
        __stcs(outA4 + idx, aA);
        __stcs(outS4 + idx, s);
    }
}

extern "C" void kernel_launch(void* const* d_in, const int* in_sizes, int n_in,
                              void* d_out, int out_size) {
    const float4* A4  = (const float4*)d_in[0];
    const float4* Bu4 = (const float4*)d_in[1];
    float4* outA4 = (float4*)d_out;
    float4* outS4 = (float4*)((float*)d_out + (size_t)TT * DD);

    s5_pass1<<<GG, V4>>>(A4, Bu4);
    s5_pass2<<<DD, GG>>>();
    s5_pass3<<<GG, V4>>>(A4, Bu4, outA4, outS4);
}

// round 7
// speedup vs baseline: 1.9930x; 1.1926x over previous
#include <cuda_runtime.h>

// S5 associative scan: (A_i,Bu_i)*(A_j,Bu_j) = (A_j*A_i, A_j*Bu_i + Bu_j)
// Per channel d:  cumA_t = A_t * cumA_{t-1},   S_t = A_t*S_{t-1} + Bu_t
// out[0:T*D] = A_scan, out[T*D:2*T*D] = Bu_scan.
//
// 3-pass chunked scan, float4-vectorized, 4 chunks per 256-thread block:
//   pass1: per-chunk aggregates (chunk-major, coalesced float4 stores)
//   pass2: 256 blocks (one per channel) x 1024 threads; each thread combines
//          4 consecutive chunk aggregates serially, Kogge-Stone over 1024,
//          then emits per-chunk EXCLUSIVE prefixes (chunk-major).
//   pass3: rescan chunks seeded with prefix, write outputs.

#define TT 131072
#define DD 256
#define GG 4096              // time chunks
#define LL (TT / GG)         // 32 rows per chunk
#define V4 (DD / 4)          // 64 float4 per row
#define CPB 4                // chunks per block (passes 1 & 3)
#define P2T (GG / 4)         // 1024 threads in pass2

// Scratch (static device arrays — allocation rules).
__device__ float g_aggA[GG * DD];    // [c][d] chunk-major
__device__ float g_aggS[GG * DD];
__device__ float g_prefA[GG * DD];   // [c][d] chunk-major (exclusive prefix)
__device__ float g_prefS[GG * DD];

// ---------------- pass 1: per-chunk aggregates ----------------
__global__ __launch_bounds__(V4 * CPB) void s5_pass1(const float4* __restrict__ A4,
                                                     const float4* __restrict__ Bu4) {
    const int sub = threadIdx.x >> 6;       // chunk within block
    const int t   = threadIdx.x & 63;       // float4 lane (channels 4t..4t+3)
    const int c   = blockIdx.x * CPB + sub;
    const size_t base = (size_t)c * LL * V4 + t;

    float4 aA = make_float4(1.f, 1.f, 1.f, 1.f);
    float4 s  = make_float4(0.f, 0.f, 0.f, 0.f);
#pragma unroll
    for (int i = 0; i < LL; ++i) {
        const float4 a  = __ldcs(A4 + base + (size_t)i * V4);
        const float4 bu = __ldcs(Bu4 + base + (size_t)i * V4);
        aA.x *= a.x; aA.y *= a.y; aA.z *= a.z; aA.w *= a.w;
        s.x = fmaf(a.x, s.x, bu.x);
        s.y = fmaf(a.y, s.y, bu.y);
        s.z = fmaf(a.z, s.z, bu.z);
        s.w = fmaf(a.w, s.w, bu.w);
    }
    ((float4*)g_aggA)[c * V4 + t] = aA;     // coalesced
    ((float4*)g_aggS)[c * V4 + t] = s;
}

// ---------------- pass 2: cross-chunk scan (one block per channel) ----------
__global__ __launch_bounds__(P2T) void s5_pass2() {
    __shared__ float shA[P2T];
    __shared__ float shS[P2T];
    const int d = blockIdx.x;
    const int c = threadIdx.x;              // owns chunks 4c..4c+3

    // serial combine of 4 consecutive chunk aggregates (keep raw copies)
    float la[4], ls[4];
    float vA = 1.f, vS = 0.f;
#pragma unroll
    for (int j = 0; j < 4; ++j) {
        const float a = g_aggA[(c * 4 + j) * DD + d];
        const float s = g_aggS[(c * 4 + j) * DD + d];
        la[j] = a; ls[j] = s;
        vS = fmaf(a, vS, s);
        vA = vA * a;
    }
    shA[c] = vA;
    shS[c] = vS;
    __syncthreads();

    // Kogge-Stone inclusive scan over 1024 thread-aggregates
#pragma unroll
    for (int off = 1; off < P2T; off <<= 1) {
        float pA = 0.f, pS = 0.f;
        const bool valid = (c >= off);
        if (valid) { pA = shA[c - off]; pS = shS[c - off]; }
        __syncthreads();
        if (valid) {
            vS = fmaf(vA, pS, vS);
            vA = vA * pA;
            shA[c] = vA;
            shS[c] = vS;
        }
        __syncthreads();
    }

    // exclusive prefix entering this thread's 4 chunks
    float eA = (c == 0) ? 1.f : shA[c - 1];
    float eS = (c == 0) ? 0.f : shS[c - 1];
#pragma unroll
    for (int j = 0; j < 4; ++j) {
        g_prefA[(c * 4 + j) * DD + d] = eA;
        g_prefS[(c * 4 + j) * DD + d] = eS;
        eS = fmaf(la[j], eS, ls[j]);
        eA = eA * la[j];
    }
}

// ---------------- pass 3: rescan with prefix, write outputs -----------------
__global__ __launch_bounds__(V4 * CPB) void s5_pass3(const float4* __restrict__ A4,
                                                     const float4* __restrict__ Bu4,
                                                     float4* __restrict__ outA4,
                                                     float4* __restrict__ outS4) {
    const int sub = threadIdx.x >> 6;
    const int t   = threadIdx.x & 63;
    const int c   = blockIdx.x * CPB + sub;
    const size_t base = (size_t)c * LL * V4 + t;

    float4 aA = ((const float4*)g_prefA)[c * V4 + t];   // coalesced
    float4 s  = ((const float4*)g_prefS)[c * V4 + t];

#pragma unroll
    for (int i = 0; i < LL; ++i) {
        const size_t idx = base + (size_t)i * V4;
        const float4 a  = __ldcs(A4 + idx);
        const float4 bu = __ldcs(Bu4 + idx);
        aA.x *= a.x; aA.y *= a.y; aA.z *= a.z; aA.w *= a.w;
        s.x = fmaf(a.x, s.x, bu.x);
        s.y = fmaf(a.y, s.y, bu.y);
        s.z = fmaf(a.z, s.z, bu.z);
        s.w = fmaf(a.w, s.w, bu.w);
        __stcs(outA4 + idx, aA);
        __stcs(outS4 + idx, s);
    }
}

extern "C" void kernel_launch(void* const* d_in, const int* in_sizes, int n_in,
                              void* d_out, int out_size) {
    const float4* A4  = (const float4*)d_in[0];
    const float4* Bu4 = (const float4*)d_in[1];
    float4* outA4 = (float4*)d_out;
    float4* outS4 = (float4*)((float*)d_out + (size_t)TT * DD);

    s5_pass1<<<GG / CPB, V4 * CPB>>>(A4, Bu4);
    s5_pass2<<<DD, P2T>>>();
    s5_pass3<<<GG / CPB, V4 * CPB>>>(A4, Bu4, outA4, outS4);
}